// round 8
// baseline (speedup 1.0000x reference)
#include <cuda_runtime.h>
#include <cuda_fp16.h>

#define NNODES 200000
#define INDIM  128
#define H1     256
#define HID    16
#define NEG    0.01f
#define EMAX   6400000
#define NB_SCAN 782          // ceil(200000/256)

// ---------------- scratch (device globals; no runtime allocation) ----------------
__device__ float  g_h   [NNODES * HID];   // MLP output
__device__ float4 g_hwh [NNODES * 2];     // fp16 message table: 16 halfs (32B) per node
__device__ float  g_agg [NNODES * HID];   // aggregation result (conv0)
__device__ float  g_dinv[NNODES];
__device__ int    g_cnt [NNODES];         // in-degree (no self loop)
__device__ int    g_off [NNODES];         // CSR row offsets (exclusive)
__device__ int    g_cur [NNODES];         // scatter cursors
__device__ int    g_srcs[EMAX];           // CSR col: src node per incoming edge
__device__ int    g_bsum[1024];
__device__ int    g_boff[1024];

__device__ __forceinline__ float lrelu(float v) { return v >= 0.f ? v : NEG * v; }

__device__ __forceinline__ int clampN(int i)
{
    i = i < 0 ? 0 : i;
    return i >= NNODES ? NNODES - 1 : i;
}

// ---- tf32 helpers -------------------------------------------------------------
__device__ __forceinline__ void split_tf32(float v, unsigned& hi, unsigned& lo)
{
    asm("cvt.rna.tf32.f32 %0, %1;" : "=r"(hi) : "f"(v));
    float r = v - __uint_as_float(hi);
    asm("cvt.rna.tf32.f32 %0, %1;" : "=r"(lo) : "f"(r));
}

#define MMA_TF32(d, a, b)                                                        \
    asm("mma.sync.aligned.m16n8k8.row.col.f32.tf32.tf32.f32 "                    \
        "{%0,%1,%2,%3},{%4,%5,%6,%7},{%8,%9},{%0,%1,%2,%3};"                     \
        : "+f"((d)[0]), "+f"((d)[1]), "+f"((d)[2]), "+f"((d)[3])                 \
        : "r"((a)[0]), "r"((a)[1]), "r"((a)[2]), "r"((a)[3]),                    \
          "r"((b)[0]), "r"((b)[1]))

// ---------------- fused tensor-core MLP ----------------------------------------
// smem layout (floats):
//  stage A: xs @0 (64x132=8448) | whi @8448 (32x264=8448) | wlo @16896 (8448)
//  stage B: h1s @0 (64x260=16640) | w2s @16640 (256x24=6144)   [loaded after stage A]
#define XS  132
#define WS  264
#define HS  260
#define W2S 24
#define SMEM_FLOATS 25344

__global__ __launch_bounds__(256) void mlp_tc_kernel(
    const float* __restrict__ x,
    const float* __restrict__ W1, const float* __restrict__ b1,
    const float* __restrict__ W2, const float* __restrict__ b2)
{
    extern __shared__ float sm[];
    float* xs  = sm;
    float* whi = sm + 8448;
    float* wlo = sm + 16896;
    float* h1s = sm;
    float* w2s = sm + 16640;

    const int tid  = threadIdx.x;
    const int wid  = tid >> 5;
    const int lane = tid & 31;
    const int g    = lane >> 2;
    const int t    = lane & 3;
    const int n0   = blockIdx.x * 64;

    {
        const float4* xg = (const float4*)(x + (size_t)n0 * INDIM);
        #pragma unroll
        for (int i = 0; i < 8; i++) {
            int lin = i * 256 + tid;
            int row = lin >> 5, c4 = (lin & 31) << 2;
            float4 v = xg[lin];
            *(float4*)(xs + row * XS + c4) = v;
        }
    }

    const int wm = wid >> 2;
    const int wn = wid & 3;
    float acc[2][8][4];
    #pragma unroll
    for (int mt = 0; mt < 2; mt++)
        #pragma unroll
        for (int nt = 0; nt < 8; nt++)
            #pragma unroll
            for (int r = 0; r < 4; r++) acc[mt][nt][r] = 0.f;

    for (int k0 = 0; k0 < INDIM; k0 += 32) {
        __syncthreads();
        {
            // stage W1 chunk [32][256], pre-split into tf32 hi/lo
            const float4* wg = (const float4*)(W1 + (size_t)k0 * H1);
            #pragma unroll
            for (int i = 0; i < 8; i++) {
                int lin = i * 256 + tid;
                int row = lin >> 6, c4 = (lin & 63) << 2;
                float4 v = wg[lin];
                unsigned h0,l0,h1,l1,h2,l2,h3,l3;
                split_tf32(v.x, h0, l0);
                split_tf32(v.y, h1, l1);
                split_tf32(v.z, h2, l2);
                split_tf32(v.w, h3, l3);
                *(float4*)(whi + row * WS + c4) = make_float4(
                    __uint_as_float(h0), __uint_as_float(h1),
                    __uint_as_float(h2), __uint_as_float(h3));
                *(float4*)(wlo + row * WS + c4) = make_float4(
                    __uint_as_float(l0), __uint_as_float(l1),
                    __uint_as_float(l2), __uint_as_float(l3));
            }
        }
        __syncthreads();

        #pragma unroll
        for (int ks = 0; ks < 32; ks += 8) {
            unsigned ahi[2][4], alo[2][4];
            #pragma unroll
            for (int mt = 0; mt < 2; mt++) {
                int rb = wm * 32 + mt * 16;
                float a0 = xs[(rb + g)     * XS + k0 + ks + t];
                float a1 = xs[(rb + g + 8) * XS + k0 + ks + t];
                float a2 = xs[(rb + g)     * XS + k0 + ks + t + 4];
                float a3 = xs[(rb + g + 8) * XS + k0 + ks + t + 4];
                split_tf32(a0, ahi[mt][0], alo[mt][0]);
                split_tf32(a1, ahi[mt][1], alo[mt][1]);
                split_tf32(a2, ahi[mt][2], alo[mt][2]);
                split_tf32(a3, ahi[mt][3], alo[mt][3]);
            }
            #pragma unroll
            for (int nt = 0; nt < 8; nt++) {
                int cb = wn * 64 + nt * 8;
                unsigned bhi[2], blo[2];
                bhi[0] = __float_as_uint(whi[(ks + t)     * WS + cb + g]);
                bhi[1] = __float_as_uint(whi[(ks + t + 4) * WS + cb + g]);
                blo[0] = __float_as_uint(wlo[(ks + t)     * WS + cb + g]);
                blo[1] = __float_as_uint(wlo[(ks + t + 4) * WS + cb + g]);
                #pragma unroll
                for (int mt = 0; mt < 2; mt++) {
                    MMA_TF32(acc[mt][nt], ahi[mt], bhi);
                    MMA_TF32(acc[mt][nt], ahi[mt], blo);
                    MMA_TF32(acc[mt][nt], alo[mt], bhi);
                }
            }
        }
    }
    __syncthreads();

    // epilogue A -> h1s, and load w2s (disjoint smem regions)
    #pragma unroll
    for (int mt = 0; mt < 2; mt++) {
        int rb = wm * 32 + mt * 16;
        #pragma unroll
        for (int nt = 0; nt < 8; nt++) {
            int cb = wn * 64 + nt * 8 + t * 2;
            float bb0 = b1[cb], bb1 = b1[cb + 1];
            h1s[(rb + g)     * HS + cb    ] = lrelu(acc[mt][nt][0] + bb0);
            h1s[(rb + g)     * HS + cb + 1] = lrelu(acc[mt][nt][1] + bb1);
            h1s[(rb + g + 8) * HS + cb    ] = lrelu(acc[mt][nt][2] + bb0);
            h1s[(rb + g + 8) * HS + cb + 1] = lrelu(acc[mt][nt][3] + bb1);
        }
    }
    {
        const float4* wg = (const float4*)W2;
        #pragma unroll
        for (int i = 0; i < 4; i++) {
            int lin = i * 256 + tid;
            int row = lin >> 2, c4 = (lin & 3) << 2;
            float4 v = wg[lin];
            *(float4*)(w2s + row * W2S + c4) = v;
        }
    }
    __syncthreads();

    {
        const int mt2 = wid >> 1;
        const int nt2 = wid & 1;
        const int rb  = mt2 * 16;
        const int cb  = nt2 * 8;
        float d[4] = {0.f, 0.f, 0.f, 0.f};

        #pragma unroll 4
        for (int k = 0; k < H1; k += 8) {
            float a0 = h1s[(rb + g)     * HS + k + t];
            float a1 = h1s[(rb + g + 8) * HS + k + t];
            float a2 = h1s[(rb + g)     * HS + k + t + 4];
            float a3 = h1s[(rb + g + 8) * HS + k + t + 4];
            unsigned ahi[4], alo[4];
            split_tf32(a0, ahi[0], alo[0]);
            split_tf32(a1, ahi[1], alo[1]);
            split_tf32(a2, ahi[2], alo[2]);
            split_tf32(a3, ahi[3], alo[3]);
            float b0f = w2s[(k + t)     * W2S + cb + g];
            float b1f = w2s[(k + t + 4) * W2S + cb + g];
            unsigned bhi[2], blo[2];
            split_tf32(b0f, bhi[0], blo[0]);
            split_tf32(b1f, bhi[1], blo[1]);
            MMA_TF32(d, ahi, bhi);
            MMA_TF32(d, ahi, blo);
            MMA_TF32(d, alo, bhi);
        }

        int col = cb + t * 2;
        float bb0 = b2[col], bb1 = b2[col + 1];
        g_h[(size_t)(n0 + rb + g)     * HID + col    ] = lrelu(d[0] + bb0);
        g_h[(size_t)(n0 + rb + g)     * HID + col + 1] = lrelu(d[1] + bb1);
        g_h[(size_t)(n0 + rb + g + 8) * HID + col    ] = lrelu(d[2] + bb0);
        g_h[(size_t)(n0 + rb + g + 8) * HID + col + 1] = lrelu(d[3] + bb1);
    }
}

// ---------------- CSR build --------------------------------------------------
__global__ void zero_cnt_kernel()
{
    int i = blockIdx.x * blockDim.x + threadIdx.x;
    if (i < NNODES) g_cnt[i] = 0;
}

__global__ void deg_count_kernel(const int* __restrict__ dst, int E)
{
    int e = blockIdx.x * blockDim.x + threadIdx.x;
    if (e < E) atomicAdd(&g_cnt[clampN(dst[e])], 1);
}

__global__ __launch_bounds__(256) void scanA_kernel()
{
    __shared__ int s[256];
    int i = blockIdx.x * 256 + threadIdx.x;
    s[threadIdx.x] = (i < NNODES) ? g_cnt[i] : 0;
    __syncthreads();
    for (int o = 128; o > 0; o >>= 1) {
        if (threadIdx.x < o) s[threadIdx.x] += s[threadIdx.x + o];
        __syncthreads();
    }
    if (threadIdx.x == 0) g_bsum[blockIdx.x] = s[0];
}

__global__ __launch_bounds__(1024) void scanB_kernel()
{
    __shared__ int s[1024];
    int tid = threadIdx.x;
    int v = (tid < NB_SCAN) ? g_bsum[tid] : 0;
    s[tid] = v;
    __syncthreads();
    for (int o = 1; o < 1024; o <<= 1) {
        int t = (tid >= o) ? s[tid - o] : 0;
        __syncthreads();
        s[tid] += t;
        __syncthreads();
    }
    if (tid < NB_SCAN) g_boff[tid] = s[tid] - v;   // exclusive
}

__global__ __launch_bounds__(256) void scanC_kernel()
{
    __shared__ int s[256];
    int tid = threadIdx.x;
    int i = blockIdx.x * 256 + tid;
    int c = (i < NNODES) ? g_cnt[i] : 0;
    s[tid] = c;
    __syncthreads();
    for (int o = 1; o < 256; o <<= 1) {
        int t = (tid >= o) ? s[tid - o] : 0;
        __syncthreads();
        s[tid] += t;
        __syncthreads();
    }
    if (i < NNODES) {
        int off = g_boff[blockIdx.x] + s[tid] - c;   // exclusive
        g_off[i] = off;
        g_cur[i] = off;
        g_dinv[i] = rsqrtf((float)(c + 1));          // +1 self loop
    }
}

__global__ void scatter_kernel(const int* __restrict__ src, const int* __restrict__ dst, int E)
{
    int e = blockIdx.x * blockDim.x + threadIdx.x;
    if (e >= E) return;
    const int s = clampN(src[e]);
    const int d = clampN(dst[e]);
    int pos = atomicAdd(&g_cur[d], 1);
    g_srcs[pos] = s;
}

// ---------------- per-conv: g_hwh = fp16( ((maybe lrelu)(in) @ cw) * dinv ) -----
__global__ __launch_bounds__(256) void conv_pre_kernel(
    int src_sel,
    const float* __restrict__ cw)
{
    __shared__ float ws[HID * HID];
    __shared__ float ht[16 * HID];

    const int tid = threadIdx.x;
    const int n0  = blockIdx.x * 16;

    if (tid < HID * HID) ws[tid] = cw[tid];
    {
        float v;
        if (src_sel == 0) v = g_h[n0 * HID + tid];
        else              v = lrelu(g_agg[n0 * HID + tid]);
        ht[tid] = v;
    }
    __syncthreads();

    const int n = tid >> 4, j = tid & 15;
    float s = 0.f;
    #pragma unroll
    for (int k = 0; k < HID; k++) s += ht[n * HID + k] * ws[k * HID + j];

    const int gn = n0 + n;
    __half* hw16 = (__half*)g_hwh;
    hw16[gn * 16 + j] = __float2half(s * g_dinv[gn]);
}

// ---------------- aggregation: warp per node, fp16 gather from CSR --------------
// agg[n] = cb + dinv[n] * ( sum_{s in srcs(n)} hwh[s] + hwh[n] )
__global__ __launch_bounds__(256) void agg_kernel(
    const float* __restrict__ cb,
    const float* __restrict__ pw, const float* __restrict__ pb,
    float* __restrict__ out, long long out_size, int last)
{
    const int wid  = threadIdx.x >> 5;
    const int lane = threadIdx.x & 31;
    const int n    = blockIdx.x * 8 + wid;
    if (n >= NNODES) return;

    const int q  = lane & 1;       // which 16B half of the 32B row
    const int es = lane >> 1;      // edge sub-slot 0..15

    const int beg = g_off[n];
    const int end = beg + g_cnt[n];

    float acc[8];
    #pragma unroll
    for (int j = 0; j < 8; j++) acc[j] = 0.f;

    for (int i = beg; i < end; i += 16) {
        int sl = -1;
        if (lane < 16 && i + lane < end) sl = g_srcs[i + lane];
        int s = __shfl_sync(0xffffffffu, sl, es);
        if (s >= 0) {
            float4 raw = g_hwh[s * 2 + q];
            const __half2* hp = (const __half2*)&raw;
            #pragma unroll
            for (int j = 0; j < 4; j++) {
                float2 f = __half22float2(hp[j]);
                acc[2*j]   += f.x;
                acc[2*j+1] += f.y;
            }
        }
    }

    #pragma unroll
    for (int o = 16; o >= 2; o >>= 1)
        #pragma unroll
        for (int j = 0; j < 8; j++)
            acc[j] += __shfl_xor_sync(0xffffffffu, acc[j], o);

    if (lane < 2) {
        float4 raw = g_hwh[n * 2 + q];
        const __half2* hp = (const __half2*)&raw;
        const float di = g_dinv[n];
        float r[8];
        #pragma unroll
        for (int j = 0; j < 4; j++) {
            float2 f = __half22float2(hp[j]);
            r[2*j]   = cb[q*8 + 2*j]   + di * (acc[2*j]   + f.x);
            r[2*j+1] = cb[q*8 + 2*j+1] + di * (acc[2*j+1] + f.y);
        }

        if (!last) {
            float4* ap = (float4*)(g_agg + (size_t)n * HID + q * 8);
            ap[0] = make_float4(r[0], r[1], r[2], r[3]);
            ap[1] = make_float4(r[4], r[5], r[6], r[7]);
        } else {
            float h[8];
            #pragma unroll
            for (int j = 0; j < 8; j++) h[j] = lrelu(r[j]);

            if (out_size >= (long long)NNODES * (1 + HID)) {
                float4* op = (float4*)(out + NNODES + (size_t)n * HID + q * 8);
                op[0] = make_float4(h[0], h[1], h[2], h[3]);
                op[1] = make_float4(h[4], h[5], h[6], h[7]);
            }

            float part = 0.f;
            #pragma unroll
            for (int j = 0; j < 8; j++) {
                int c = q * 8 + j;
                part += h[j] * (__ldg(pw + 2*c) + __ldg(pw + 2*c + 1));
            }
            part += __shfl_xor_sync(0x00000003u, part, 1);
            if (lane == 0) out[n] = part + pb[0] + pb[1];
        }
    }
}

// ---------------- launch: fork-join across two streams ---------------------------
extern "C" void kernel_launch(void* const* d_in, const int* in_sizes, int n_in,
                              void* d_out, int out_size)
{
    const float *x = 0, *W1 = 0, *b1 = 0, *W2 = 0, *b2 = 0;
    const float *cw0 = 0, *cb0 = 0, *cw1 = 0, *cb1 = 0, *pw = 0, *pb = 0;
    const void  *edges = 0;
    long long    edge_elems = 0;

    int n256 = 0, n16 = 0;
    for (int i = 0; i < n_in; i++) {
        const long long sz = in_sizes[i];
        const void* p = d_in[i];
        switch (sz) {
            case 25600000LL: x  = (const float*)p; break;
            case 32768LL:    W1 = (const float*)p; break;
            case 4096LL:     W2 = (const float*)p; break;
            case 32LL:       pw = (const float*)p; break;
            case 2LL:        pb = (const float*)p; break;
            case 256LL:
                if      (n256 == 0) b1  = (const float*)p;
                else if (n256 == 1) cw0 = (const float*)p;
                else                cw1 = (const float*)p;
                n256++; break;
            case 16LL:
                if      (n16 == 0) b2  = (const float*)p;
                else if (n16 == 1) cb0 = (const float*)p;
                else               cb1 = (const float*)p;
                n16++; break;
            default:
                if (sz > 1000000LL) { edges = p; edge_elems = sz; }
                break;
        }
    }

    int E = (int)(edge_elems / 2);
    if (E > EMAX) E = EMAX;
    const int* srcp = (const int*)edges;
    const int* dstp = (const int*)edges + E;

    float* out = (float*)d_out;

    const int NB_NODES16 = NNODES / 16;
    const int NB_NODES   = (NNODES + 255) / 256;
    const int NB_EDGES   = (E + 255) / 256;
    const int NB_AGG     = (NNODES + 7) / 8;

    static int inited = 0;
    static cudaStream_t s2 = 0;
    static cudaEvent_t  evRoot = 0, evScanC = 0, evCsr = 0;
    if (!inited) {
        cudaFuncSetAttribute(mlp_tc_kernel,
                             cudaFuncAttributeMaxDynamicSharedMemorySize,
                             SMEM_FLOATS * 4);
        cudaStreamCreateWithFlags(&s2, cudaStreamNonBlocking);
        cudaEventCreateWithFlags(&evRoot,  cudaEventDisableTiming);
        cudaEventCreateWithFlags(&evScanC, cudaEventDisableTiming);
        cudaEventCreateWithFlags(&evCsr,   cudaEventDisableTiming);
        inited = 1;
    }

    // fork: s2 runs the CSR build while stream0 runs the MLP
    cudaEventRecord(evRoot, 0);
    cudaStreamWaitEvent(s2, evRoot, 0);

    zero_cnt_kernel <<<NB_NODES, 256, 0, s2>>>();
    deg_count_kernel<<<NB_EDGES, 256, 0, s2>>>(dstp, E);
    scanA_kernel    <<<NB_SCAN, 256, 0, s2>>>();
    scanB_kernel    <<<1, 1024, 0, s2>>>();
    scanC_kernel    <<<NB_SCAN, 256, 0, s2>>>();
    cudaEventRecord(evScanC, s2);
    scatter_kernel  <<<NB_EDGES, 256, 0, s2>>>(srcp, dstp, E);
    cudaEventRecord(evCsr, s2);

    mlp_tc_kernel<<<NNODES / 64, 256, SMEM_FLOATS * 4>>>(x, W1, b1, W2, b2);

    cudaStreamWaitEvent(0, evScanC, 0);
    conv_pre_kernel<<<NB_NODES16, 256>>>(0, cw0);

    cudaStreamWaitEvent(0, evCsr, 0);
    agg_kernel<<<NB_AGG, 256>>>(cb0, pw, pb, out, (long long)out_size, 0);

    conv_pre_kernel<<<NB_NODES16, 256>>>(1, cw1);
    agg_kernel<<<NB_AGG, 256>>>(cb1, pw, pb, out, (long long)out_size, 1);
}

// round 9
// speedup vs baseline: 1.5229x; 1.5229x over previous
#include <cuda_runtime.h>
#include <cuda_fp16.h>

#define NNODES 200000
#define INDIM  128
#define H1     256
#define HID    16
#define NEG    0.01f
#define EMAX   6400000
#define NB_SCAN 782          // ceil(200000/256)

// ---------------- scratch (device globals; no runtime allocation) ----------------
__device__ float g_h   [NNODES * HID];   // MLP output
__device__ uint4 g_hwh [NNODES * 2];     // fp16 message table: 16 halfs (32B) per node
__device__ float g_agg [NNODES * HID];   // aggregation result (conv0)
__device__ float g_dinv[NNODES];
__device__ int   g_cnt [NNODES];         // in-degree (no self loop)
__device__ int   g_off [NNODES];         // CSR row offsets (exclusive)
__device__ int   g_cur [NNODES];         // scatter cursors
__device__ int   g_srcs[EMAX];           // CSR col: src node per incoming edge
__device__ int   g_bsum[1024];
__device__ int   g_boff[1024];

__device__ __forceinline__ float lrelu(float v) { return v >= 0.f ? v : NEG * v; }

__device__ __forceinline__ int clampN(int i)
{
    i = i < 0 ? 0 : i;
    return i >= NNODES ? NNODES - 1 : i;
}

// register-safe packed-half -> 2 floats (no address-of, no local memory)
__device__ __forceinline__ void h2_to_f2(unsigned w, float& f0, float& f1)
{
    asm("{\n\t.reg .b16 lo, hi;\n\t"
        "mov.b32 {lo, hi}, %2;\n\t"
        "cvt.f32.f16 %0, lo;\n\t"
        "cvt.f32.f16 %1, hi;\n\t}"
        : "=f"(f0), "=f"(f1) : "r"(w));
}

// ---- tf32 helpers -------------------------------------------------------------
__device__ __forceinline__ void split_tf32(float v, unsigned& hi, unsigned& lo)
{
    asm("cvt.rna.tf32.f32 %0, %1;" : "=r"(hi) : "f"(v));
    float r = v - __uint_as_float(hi);
    asm("cvt.rna.tf32.f32 %0, %1;" : "=r"(lo) : "f"(r));
}

#define MMA_TF32(d, a, b)                                                        \
    asm("mma.sync.aligned.m16n8k8.row.col.f32.tf32.tf32.f32 "                    \
        "{%0,%1,%2,%3},{%4,%5,%6,%7},{%8,%9},{%0,%1,%2,%3};"                     \
        : "+f"((d)[0]), "+f"((d)[1]), "+f"((d)[2]), "+f"((d)[3])                 \
        : "r"((a)[0]), "r"((a)[1]), "r"((a)[2]), "r"((a)[3]),                    \
          "r"((b)[0]), "r"((b)[1]))

// ---------------- fused tensor-core MLP (R7-proven version) ----------------------
#define XS  132
#define WS  264
#define HS  260
#define W2S 24
#define SMEM_FLOATS (16896 + 6144)

__global__ __launch_bounds__(256) void mlp_tc_kernel(
    const float* __restrict__ x,
    const float* __restrict__ W1, const float* __restrict__ b1,
    const float* __restrict__ W2, const float* __restrict__ b2)
{
    extern __shared__ float sm[];
    float* xs  = sm;
    float* wsm = sm + 8448;
    float* h1s = sm;
    float* w2s = sm + 16896;

    const int tid  = threadIdx.x;
    const int wid  = tid >> 5;
    const int lane = tid & 31;
    const int g    = lane >> 2;
    const int t    = lane & 3;
    const int n0   = blockIdx.x * 64;

    {
        const float4* xg = (const float4*)(x + (size_t)n0 * INDIM);
        #pragma unroll
        for (int i = 0; i < 8; i++) {
            int lin = i * 256 + tid;
            int row = lin >> 5, c4 = (lin & 31) << 2;
            float4 v = xg[lin];
            *(float4*)(xs + row * XS + c4) = v;
        }
        const float4* wg = (const float4*)W2;
        #pragma unroll
        for (int i = 0; i < 4; i++) {
            int lin = i * 256 + tid;
            int row = lin >> 2, c4 = (lin & 3) << 2;
            float4 v = wg[lin];
            *(float4*)(w2s + row * W2S + c4) = v;
        }
    }

    const int wm = wid >> 2;
    const int wn = wid & 3;
    float acc[2][8][4];
    #pragma unroll
    for (int mt = 0; mt < 2; mt++)
        #pragma unroll
        for (int nt = 0; nt < 8; nt++)
            #pragma unroll
            for (int r = 0; r < 4; r++) acc[mt][nt][r] = 0.f;

    for (int k0 = 0; k0 < INDIM; k0 += 32) {
        __syncthreads();
        {
            const float4* wg = (const float4*)(W1 + (size_t)k0 * H1);
            #pragma unroll
            for (int i = 0; i < 8; i++) {
                int lin = i * 256 + tid;
                int row = lin >> 6, c4 = (lin & 63) << 2;
                float4 v = wg[lin];
                *(float4*)(wsm + row * WS + c4) = v;
            }
        }
        __syncthreads();

        #pragma unroll
        for (int ks = 0; ks < 32; ks += 8) {
            unsigned ahi[2][4], alo[2][4];
            #pragma unroll
            for (int mt = 0; mt < 2; mt++) {
                int rb = wm * 32 + mt * 16;
                float a0 = xs[(rb + g)     * XS + k0 + ks + t];
                float a1 = xs[(rb + g + 8) * XS + k0 + ks + t];
                float a2 = xs[(rb + g)     * XS + k0 + ks + t + 4];
                float a3 = xs[(rb + g + 8) * XS + k0 + ks + t + 4];
                split_tf32(a0, ahi[mt][0], alo[mt][0]);
                split_tf32(a1, ahi[mt][1], alo[mt][1]);
                split_tf32(a2, ahi[mt][2], alo[mt][2]);
                split_tf32(a3, ahi[mt][3], alo[mt][3]);
            }
            #pragma unroll
            for (int nt = 0; nt < 8; nt++) {
                int cb = wn * 64 + nt * 8;
                float b0f = wsm[(ks + t)     * WS + cb + g];
                float b1f = wsm[(ks + t + 4) * WS + cb + g];
                unsigned bhi[2], blo[2];
                split_tf32(b0f, bhi[0], blo[0]);
                split_tf32(b1f, bhi[1], blo[1]);
                #pragma unroll
                for (int mt = 0; mt < 2; mt++) {
                    MMA_TF32(acc[mt][nt], ahi[mt], bhi);
                    MMA_TF32(acc[mt][nt], ahi[mt], blo);
                    MMA_TF32(acc[mt][nt], alo[mt], bhi);
                }
            }
        }
    }
    __syncthreads();

    #pragma unroll
    for (int mt = 0; mt < 2; mt++) {
        int rb = wm * 32 + mt * 16;
        #pragma unroll
        for (int nt = 0; nt < 8; nt++) {
            int cb = wn * 64 + nt * 8 + t * 2;
            float bb0 = b1[cb], bb1 = b1[cb + 1];
            h1s[(rb + g)     * HS + cb    ] = lrelu(acc[mt][nt][0] + bb0);
            h1s[(rb + g)     * HS + cb + 1] = lrelu(acc[mt][nt][1] + bb1);
            h1s[(rb + g + 8) * HS + cb    ] = lrelu(acc[mt][nt][2] + bb0);
            h1s[(rb + g + 8) * HS + cb + 1] = lrelu(acc[mt][nt][3] + bb1);
        }
    }
    __syncthreads();

    {
        const int mt2 = wid >> 1;
        const int nt2 = wid & 1;
        const int rb  = mt2 * 16;
        const int cb  = nt2 * 8;
        float d[4] = {0.f, 0.f, 0.f, 0.f};

        #pragma unroll 4
        for (int k = 0; k < H1; k += 8) {
            float a0 = h1s[(rb + g)     * HS + k + t];
            float a1 = h1s[(rb + g + 8) * HS + k + t];
            float a2 = h1s[(rb + g)     * HS + k + t + 4];
            float a3 = h1s[(rb + g + 8) * HS + k + t + 4];
            unsigned ahi[4], alo[4];
            split_tf32(a0, ahi[0], alo[0]);
            split_tf32(a1, ahi[1], alo[1]);
            split_tf32(a2, ahi[2], alo[2]);
            split_tf32(a3, ahi[3], alo[3]);
            float b0f = w2s[(k + t)     * W2S + cb + g];
            float b1f = w2s[(k + t + 4) * W2S + cb + g];
            unsigned bhi[2], blo[2];
            split_tf32(b0f, bhi[0], blo[0]);
            split_tf32(b1f, bhi[1], blo[1]);
            MMA_TF32(d, ahi, bhi);
            MMA_TF32(d, ahi, blo);
            MMA_TF32(d, alo, bhi);
        }

        int col = cb + t * 2;
        float bb0 = b2[col], bb1 = b2[col + 1];
        g_h[(size_t)(n0 + rb + g)     * HID + col    ] = lrelu(d[0] + bb0);
        g_h[(size_t)(n0 + rb + g)     * HID + col + 1] = lrelu(d[1] + bb1);
        g_h[(size_t)(n0 + rb + g + 8) * HID + col    ] = lrelu(d[2] + bb0);
        g_h[(size_t)(n0 + rb + g + 8) * HID + col + 1] = lrelu(d[3] + bb1);
    }
}

// ---------------- CSR build --------------------------------------------------
__global__ void zero_cnt_kernel()
{
    int i = blockIdx.x * blockDim.x + threadIdx.x;
    if (i < NNODES) g_cnt[i] = 0;
}

__global__ void deg_count_kernel(const int* __restrict__ dst, int E)
{
    int e = blockIdx.x * blockDim.x + threadIdx.x;
    if (e < E) atomicAdd(&g_cnt[clampN(dst[e])], 1);
}

__global__ __launch_bounds__(256) void scanA_kernel()
{
    __shared__ int s[256];
    int i = blockIdx.x * 256 + threadIdx.x;
    s[threadIdx.x] = (i < NNODES) ? g_cnt[i] : 0;
    __syncthreads();
    for (int o = 128; o > 0; o >>= 1) {
        if (threadIdx.x < o) s[threadIdx.x] += s[threadIdx.x + o];
        __syncthreads();
    }
    if (threadIdx.x == 0) g_bsum[blockIdx.x] = s[0];
}

__global__ __launch_bounds__(1024) void scanB_kernel()
{
    __shared__ int s[1024];
    int tid = threadIdx.x;
    int v = (tid < NB_SCAN) ? g_bsum[tid] : 0;
    s[tid] = v;
    __syncthreads();
    for (int o = 1; o < 1024; o <<= 1) {
        int t = (tid >= o) ? s[tid - o] : 0;
        __syncthreads();
        s[tid] += t;
        __syncthreads();
    }
    if (tid < NB_SCAN) g_boff[tid] = s[tid] - v;   // exclusive
}

__global__ __launch_bounds__(256) void scanC_kernel()
{
    __shared__ int s[256];
    int tid = threadIdx.x;
    int i = blockIdx.x * 256 + tid;
    int c = (i < NNODES) ? g_cnt[i] : 0;
    s[tid] = c;
    __syncthreads();
    for (int o = 1; o < 256; o <<= 1) {
        int t = (tid >= o) ? s[tid - o] : 0;
        __syncthreads();
        s[tid] += t;
        __syncthreads();
    }
    if (i < NNODES) {
        int off = g_boff[blockIdx.x] + s[tid] - c;   // exclusive
        g_off[i] = off;
        g_cur[i] = off;
        g_dinv[i] = rsqrtf((float)(c + 1));          // +1 self loop
    }
}

__global__ void scatter_kernel(const int* __restrict__ src, const int* __restrict__ dst, int E)
{
    int e = blockIdx.x * blockDim.x + threadIdx.x;
    if (e >= E) return;
    const int s = clampN(src[e]);
    const int d = clampN(dst[e]);
    int pos = atomicAdd(&g_cur[d], 1);
    g_srcs[pos] = s;
}

// ---------------- per-conv: g_hwh = fp16( ((maybe lrelu)(in) @ cw) * dinv ) -----
__global__ __launch_bounds__(256) void conv_pre_kernel(
    int src_sel,
    const float* __restrict__ cw)
{
    __shared__ float ws[HID * HID];
    __shared__ float ht[16 * HID];

    const int tid = threadIdx.x;
    const int n0  = blockIdx.x * 16;

    if (tid < HID * HID) ws[tid] = cw[tid];
    {
        float v;
        if (src_sel == 0) v = g_h[n0 * HID + tid];
        else              v = lrelu(g_agg[n0 * HID + tid]);
        ht[tid] = v;
    }
    __syncthreads();

    const int n = tid >> 4, j = tid & 15;
    float s = 0.f;
    #pragma unroll
    for (int k = 0; k < HID; k++) s += ht[n * HID + k] * ws[k * HID + j];

    const int gn = n0 + n;
    ((__half*)g_hwh)[gn * 16 + j] = __float2half(s * g_dinv[gn]);
}

// ---------------- aggregation: warp per node, fp16 gather (register-safe cvt) ---
// agg[n] = cb + dinv[n] * ( sum_{s in srcs(n)} hwh[s] + hwh[n] )
__global__ __launch_bounds__(256) void agg_kernel(
    const float* __restrict__ cb,
    const float* __restrict__ pw, const float* __restrict__ pb,
    float* __restrict__ out, long long out_size, int last)
{
    const int wid  = threadIdx.x >> 5;
    const int lane = threadIdx.x & 31;
    const int n    = blockIdx.x * 8 + wid;
    if (n >= NNODES) return;

    const int q  = lane & 1;       // which 16B half of the 32B row
    const int es = lane >> 1;      // edge sub-slot 0..15

    const int beg = g_off[n];
    const int end = beg + g_cnt[n];

    float a0 = 0.f, a1 = 0.f, a2 = 0.f, a3 = 0.f;
    float a4 = 0.f, a5 = 0.f, a6 = 0.f, a7 = 0.f;

    for (int i = beg; i < end; i += 16) {
        int sl = -1;
        if (lane < 16 && i + lane < end) sl = g_srcs[i + lane];
        int s = __shfl_sync(0xffffffffu, sl, es);
        if (s >= 0) {
            uint4 raw = g_hwh[s * 2 + q];
            float f0, f1;
            h2_to_f2(raw.x, f0, f1); a0 += f0; a1 += f1;
            h2_to_f2(raw.y, f0, f1); a2 += f0; a3 += f1;
            h2_to_f2(raw.z, f0, f1); a4 += f0; a5 += f1;
            h2_to_f2(raw.w, f0, f1); a6 += f0; a7 += f1;
        }
    }

    #pragma unroll
    for (int o = 16; o >= 2; o >>= 1) {
        a0 += __shfl_xor_sync(0xffffffffu, a0, o);
        a1 += __shfl_xor_sync(0xffffffffu, a1, o);
        a2 += __shfl_xor_sync(0xffffffffu, a2, o);
        a3 += __shfl_xor_sync(0xffffffffu, a3, o);
        a4 += __shfl_xor_sync(0xffffffffu, a4, o);
        a5 += __shfl_xor_sync(0xffffffffu, a5, o);
        a6 += __shfl_xor_sync(0xffffffffu, a6, o);
        a7 += __shfl_xor_sync(0xffffffffu, a7, o);
    }

    if (lane < 2) {
        uint4 raw = g_hwh[n * 2 + q];
        const float di = g_dinv[n];
        float s0, s1, s2, s3, s4, s5, s6, s7;
        h2_to_f2(raw.x, s0, s1);
        h2_to_f2(raw.y, s2, s3);
        h2_to_f2(raw.z, s4, s5);
        h2_to_f2(raw.w, s6, s7);

        const int c0 = q * 8;
        float r0 = cb[c0+0] + di * (a0 + s0);
        float r1 = cb[c0+1] + di * (a1 + s1);
        float r2 = cb[c0+2] + di * (a2 + s2);
        float r3 = cb[c0+3] + di * (a3 + s3);
        float r4 = cb[c0+4] + di * (a4 + s4);
        float r5 = cb[c0+5] + di * (a5 + s5);
        float r6 = cb[c0+6] + di * (a6 + s6);
        float r7 = cb[c0+7] + di * (a7 + s7);

        if (!last) {
            float4* ap = (float4*)(g_agg + (size_t)n * HID + c0);
            ap[0] = make_float4(r0, r1, r2, r3);
            ap[1] = make_float4(r4, r5, r6, r7);
        } else {
            float h0 = lrelu(r0), h1 = lrelu(r1), h2 = lrelu(r2), h3 = lrelu(r3);
            float h4 = lrelu(r4), h5 = lrelu(r5), h6 = lrelu(r6), h7 = lrelu(r7);

            if (out_size >= (long long)NNODES * (1 + HID)) {
                float4* op = (float4*)(out + NNODES + (size_t)n * HID + c0);
                op[0] = make_float4(h0, h1, h2, h3);
                op[1] = make_float4(h4, h5, h6, h7);
            }

            float part =
                  h0 * (__ldg(pw + 2*(c0+0)) + __ldg(pw + 2*(c0+0)+1))
                + h1 * (__ldg(pw + 2*(c0+1)) + __ldg(pw + 2*(c0+1)+1))
                + h2 * (__ldg(pw + 2*(c0+2)) + __ldg(pw + 2*(c0+2)+1))
                + h3 * (__ldg(pw + 2*(c0+3)) + __ldg(pw + 2*(c0+3)+1))
                + h4 * (__ldg(pw + 2*(c0+4)) + __ldg(pw + 2*(c0+4)+1))
                + h5 * (__ldg(pw + 2*(c0+5)) + __ldg(pw + 2*(c0+5)+1))
                + h6 * (__ldg(pw + 2*(c0+6)) + __ldg(pw + 2*(c0+6)+1))
                + h7 * (__ldg(pw + 2*(c0+7)) + __ldg(pw + 2*(c0+7)+1));
            part += __shfl_xor_sync(0x00000003u, part, 1);
            if (lane == 0) out[n] = part + pb[0] + pb[1];
        }
    }
}

// ---------------- launch: fork-join across two streams ---------------------------
extern "C" void kernel_launch(void* const* d_in, const int* in_sizes, int n_in,
                              void* d_out, int out_size)
{
    const float *x = 0, *W1 = 0, *b1 = 0, *W2 = 0, *b2 = 0;
    const float *cw0 = 0, *cb0 = 0, *cw1 = 0, *cb1 = 0, *pw = 0, *pb = 0;
    const void  *edges = 0;
    long long    edge_elems = 0;

    int n256 = 0, n16 = 0;
    for (int i = 0; i < n_in; i++) {
        const long long sz = in_sizes[i];
        const void* p = d_in[i];
        switch (sz) {
            case 25600000LL: x  = (const float*)p; break;
            case 32768LL:    W1 = (const float*)p; break;
            case 4096LL:     W2 = (const float*)p; break;
            case 32LL:       pw = (const float*)p; break;
            case 2LL:        pb = (const float*)p; break;
            case 256LL:
                if      (n256 == 0) b1  = (const float*)p;
                else if (n256 == 1) cw0 = (const float*)p;
                else                cw1 = (const float*)p;
                n256++; break;
            case 16LL:
                if      (n16 == 0) b2  = (const float*)p;
                else if (n16 == 1) cb0 = (const float*)p;
                else               cb1 = (const float*)p;
                n16++; break;
            default:
                if (sz > 1000000LL) { edges = p; edge_elems = sz; }
                break;
        }
    }

    int E = (int)(edge_elems / 2);
    if (E > EMAX) E = EMAX;
    const int* srcp = (const int*)edges;
    const int* dstp = (const int*)edges + E;

    float* out = (float*)d_out;

    const int NB_NODES16 = NNODES / 16;
    const int NB_NODES   = (NNODES + 255) / 256;
    const int NB_EDGES   = (E + 255) / 256;
    const int NB_AGG     = (NNODES + 7) / 8;

    static int inited = 0;
    static cudaStream_t s2 = 0;
    static cudaEvent_t  evRoot = 0, evScanC = 0, evCsr = 0;
    if (!inited) {
        cudaFuncSetAttribute(mlp_tc_kernel,
                             cudaFuncAttributeMaxDynamicSharedMemorySize,
                             SMEM_FLOATS * 4);
        cudaStreamCreateWithFlags(&s2, cudaStreamNonBlocking);
        cudaEventCreateWithFlags(&evRoot,  cudaEventDisableTiming);
        cudaEventCreateWithFlags(&evScanC, cudaEventDisableTiming);
        cudaEventCreateWithFlags(&evCsr,   cudaEventDisableTiming);
        inited = 1;
    }

    // fork: s2 runs the CSR build while stream0 runs the MLP
    cudaEventRecord(evRoot, 0);
    cudaStreamWaitEvent(s2, evRoot, 0);

    zero_cnt_kernel <<<NB_NODES, 256, 0, s2>>>();
    deg_count_kernel<<<NB_EDGES, 256, 0, s2>>>(dstp, E);
    scanA_kernel    <<<NB_SCAN, 256, 0, s2>>>();
    scanB_kernel    <<<1, 1024, 0, s2>>>();
    scanC_kernel    <<<NB_SCAN, 256, 0, s2>>>();
    cudaEventRecord(evScanC, s2);
    scatter_kernel  <<<NB_EDGES, 256, 0, s2>>>(srcp, dstp, E);
    cudaEventRecord(evCsr, s2);

    mlp_tc_kernel<<<NNODES / 64, 256, SMEM_FLOATS * 4>>>(x, W1, b1, W2, b2);

    cudaStreamWaitEvent(0, evScanC, 0);
    conv_pre_kernel<<<NB_NODES16, 256>>>(0, cw0);

    cudaStreamWaitEvent(0, evCsr, 0);
    agg_kernel<<<NB_AGG, 256>>>(cb0, pw, pb, out, (long long)out_size, 0);

    conv_pre_kernel<<<NB_NODES16, 256>>>(1, cw1);
    agg_kernel<<<NB_AGG, 256>>>(cb1, pw, pb, out, (long long)out_size, 1);
}